// round 15
// baseline (speedup 1.0000x reference)
#include <cuda_runtime.h>
#include <cuda_bf16.h>
#include <math.h>
#include <stdint.h>

typedef __nv_bfloat16 bf16;

#define BB 256
#define TT 40
#define VV 5000
#define DD 512
#define ZZ 128
#define NBLK 276   // 128 cell1 + 20 idle + 128 cell0

// ---------------- device scratch (static; no allocation) ----------------
__device__ bf16 s_Wg0b[4*512*1152];
__device__ bf16 s_Wg1b[4*512*1024];
__device__ bf16 s_Woutb[5000*640];
__device__ bf16 s_tw1b[2*2048*128];
__device__ bf16 s_tw2b[2*1024*2048];
__device__ bf16 s_embb[5000*512];
__device__ bf16 s_zb[256*128];
__device__ bf16 s_h0d[2][256*512];
__device__ bf16 s_h1d[2][256*512];
__device__ bf16 s_Hall[39*256*512];      // H(t) for t=0..38
__device__ bf16 s_r[256*2048];
__device__ float s_c0[256*512];
__device__ float s_c1[256*512];
__device__ float s_gz0[256*2048];
__device__ float s_hh[256*1024];
__device__ float s_embW[5000*2048];      // emb @ W0e^T  (vocab-level, fp32)
__device__ float s_zlog[256*5000];       // z @ WoutZ^T + bout
__device__ float s_lp[39*256];
__device__ int   s_idx[40*256];
__device__ unsigned g_ctr[4*32];         // per-row-block monotonic barrier counters
__device__ unsigned g_witem;

// ---------------- mma / async helpers ----------------
__device__ __forceinline__ unsigned smem_addr(const void* p){
    return (unsigned)__cvta_generic_to_shared(p);
}
__device__ __forceinline__ void ldsm4(uint32_t& r0, uint32_t& r1, uint32_t& r2, uint32_t& r3, unsigned a){
    asm volatile("ldmatrix.sync.aligned.m8n8.x4.shared.b16 {%0,%1,%2,%3}, [%4];"
                 : "=r"(r0),"=r"(r1),"=r"(r2),"=r"(r3) : "r"(a));
}
__device__ __forceinline__ void ldsm2(uint32_t& r0, uint32_t& r1, unsigned a){
    asm volatile("ldmatrix.sync.aligned.m8n8.x2.shared.b16 {%0,%1}, [%2];"
                 : "=r"(r0),"=r"(r1) : "r"(a));
}
__device__ __forceinline__ void mma_bf16(float c[4], uint32_t a0,uint32_t a1,uint32_t a2,uint32_t a3,
                                         uint32_t b0,uint32_t b1){
    asm volatile("mma.sync.aligned.m16n8k16.row.col.f32.bf16.bf16.f32 "
                 "{%0,%1,%2,%3}, {%4,%5,%6,%7}, {%8,%9}, {%0,%1,%2,%3};"
                 : "+f"(c[0]),"+f"(c[1]),"+f"(c[2]),"+f"(c[3])
                 : "r"(a0),"r"(a1),"r"(a2),"r"(a3),"r"(b0),"r"(b1));
}
__device__ __forceinline__ void cpa16(unsigned dst, const void* src){
    asm volatile("cp.async.cg.shared.global [%0], [%1], 16;" :: "r"(dst), "l"(src));
}
__device__ __forceinline__ void cpa_commit(){ asm volatile("cp.async.commit_group;"); }
__device__ __forceinline__ void cpa_wait2(){ asm volatile("cp.async.wait_group 2;"); }
__device__ __forceinline__ float sigf(float x){ return 1.f / (1.f + __expf(-x)); }
__device__ __forceinline__ float tanhfast(float x){
    float y; asm("tanh.approx.f32 %0, %1;" : "=f"(y) : "f"(x)); return y;
}
__device__ __forceinline__ float sigfast(float x){
    return fmaf(tanhfast(0.5f * x), 0.5f, 0.5f);
}

// ---------------- generic bf16 TN GEMM (64x64, prework/small) ----------------
__global__ __launch_bounds__(128)
void gemm_kernel(int M, int N, int K,
                 const bf16* __restrict__ A, int lda, const int* __restrict__ aidx,
                 const bf16* __restrict__ B, int ldb,
                 const float* __restrict__ bias,
                 const float* __restrict__ Dadd, int ldd, int dmask,
                 float* __restrict__ Cf, bf16* __restrict__ Cb, int ldc, int op)
{
    __shared__ bf16 As[2][64][40];
    __shared__ bf16 Bs[2][64][40];
    const int t  = threadIdx.x;
    const int m0 = blockIdx.y << 6, n0 = blockIdx.x << 6;
    const int ar0 = t >> 2;
    const int ak0 = (t & 3) << 3;

    long arow0 = aidx ? (long)aidx[m0 + ar0]      : (long)(m0 + ar0);
    long arow1 = aidx ? (long)aidx[m0 + ar0 + 32] : (long)(m0 + ar0 + 32);
    const bf16* Ap0 = A + arow0 * lda + ak0;
    const bf16* Ap1 = A + arow1 * lda + ak0;
    const bool bv0 = (n0 + ar0)      < N;
    const bool bv1 = (n0 + ar0 + 32) < N;
    const bf16* Bp0 = B + (long)(n0 + ar0)      * ldb + ak0;
    const bf16* Bp1 = B + (long)(n0 + ar0 + 32) * ldb + ak0;

    const int warp = t >> 5, lane = t & 31;
    const int wm = (warp >> 1) << 5, wn = (warp & 1) << 5;
    const int a_mr = lane & 15, a_kf = (lane >> 4) << 3;
    const int b_nr = lane & 7,  b_kf = ((lane >> 3) & 1) << 3;

    float acc[2][4][4];
#pragma unroll
    for (int i = 0; i < 2; i++)
#pragma unroll
        for (int j = 0; j < 4; j++)
#pragma unroll
            for (int e = 0; e < 4; e++) acc[i][j][e] = 0.f;

    const uint4 z4 = make_uint4(0u,0u,0u,0u);
    uint4 av0 = *(const uint4*)Ap0;
    uint4 av1 = *(const uint4*)Ap1;
    uint4 bw0 = bv0 ? *(const uint4*)Bp0 : z4;
    uint4 bw1 = bv1 ? *(const uint4*)Bp1 : z4;
    *(uint4*)&As[0][ar0][ak0]      = av0;
    *(uint4*)&As[0][ar0 + 32][ak0] = av1;
    *(uint4*)&Bs[0][ar0][ak0]      = bw0;
    *(uint4*)&Bs[0][ar0 + 32][ak0] = bw1;

    const int nk = K >> 5;
    int buf = 0;
    for (int kt = 0; kt < nk; ++kt) {
        __syncthreads();
        const bool more = (kt + 1) < nk;
        if (more) {
            const int kk = (kt + 1) << 5;
            av0 = *(const uint4*)(Ap0 + kk);
            av1 = *(const uint4*)(Ap1 + kk);
            bw0 = bv0 ? *(const uint4*)(Bp0 + kk) : z4;
            bw1 = bv1 ? *(const uint4*)(Bp1 + kk) : z4;
        }
#pragma unroll
        for (int ks = 0; ks < 32; ks += 16) {
            uint32_t af[2][4], bfr[4][2];
#pragma unroll
            for (int mi = 0; mi < 2; mi++)
                ldsm4(af[mi][0], af[mi][1], af[mi][2], af[mi][3],
                      smem_addr(&As[buf][wm + mi*16 + a_mr][ks + a_kf]));
#pragma unroll
            for (int ni = 0; ni < 4; ni++)
                ldsm2(bfr[ni][0], bfr[ni][1],
                      smem_addr(&Bs[buf][wn + ni*8 + b_nr][ks + b_kf]));
#pragma unroll
            for (int mi = 0; mi < 2; mi++)
#pragma unroll
                for (int ni = 0; ni < 4; ni++)
                    mma_bf16(acc[mi][ni], af[mi][0], af[mi][1], af[mi][2], af[mi][3],
                             bfr[ni][0], bfr[ni][1]);
        }
        if (more) {
            *(uint4*)&As[buf^1][ar0][ak0]      = av0;
            *(uint4*)&As[buf^1][ar0 + 32][ak0] = av1;
            *(uint4*)&Bs[buf^1][ar0][ak0]      = bw0;
            *(uint4*)&Bs[buf^1][ar0 + 32][ak0] = bw1;
        }
        buf ^= 1;
    }

    const int rbase = m0 + wm + (lane >> 2);
    const int cbase = n0 + wn + ((lane & 3) << 1);
#pragma unroll
    for (int mi = 0; mi < 2; mi++)
#pragma unroll
        for (int ni = 0; ni < 4; ni++)
#pragma unroll
            for (int e = 0; e < 4; e++) {
                int r = rbase + mi*16 + (e >> 1) * 8;
                int c = cbase + ni*8 + (e & 1);
                if (c < N) {
                    float v = acc[mi][ni][e];
                    if (bias) v += __ldg(bias + c);
                    if (Dadd) v += Dadd[(long)(r & dmask) * ldd + c];
                    if (op == 1) v = fmaxf(v, 0.f);
                    else if (op == 2) v = tanhf(v);
                    if (Cf) Cf[(long)r * ldc + c] = v;
                    if (Cb) Cb[(long)r * ldc + c] = __float2bfloat16(v);
                }
            }
}

// ---------------- big 128x128-tile GEMM: C = A*B^T (M-guarded) ----------------
__global__ __launch_bounds__(256)
void gemm128_kernel(int M, int N, int K,
                    const bf16* __restrict__ A, int lda,
                    const bf16* __restrict__ B, int ldb,
                    float* __restrict__ Cf, int ldc)
{
    __shared__ bf16 As[2][128][40];
    __shared__ bf16 Bs[2][128][40];
    const int t  = threadIdx.x;
    const int m0 = blockIdx.y << 7, n0 = blockIdx.x << 7;
    const int lr = t >> 1;
    const int lc = (t & 1) << 4;

    int arow = m0 + lr; if (arow >= M) arow = M - 1;
    const bf16* Ap = A + (long)arow * lda + lc;
    const bf16* Bp = B + (long)(n0 + lr) * ldb + lc;

    const int warp = t >> 5, lane = t & 31;
    const int wm = warp & 3, wn = warp >> 2;

    float acc[2][8][4];
#pragma unroll
    for (int mi = 0; mi < 2; mi++)
#pragma unroll
        for (int ni = 0; ni < 8; ni++)
#pragma unroll
            for (int e = 0; e < 4; e++) acc[mi][ni][e] = 0.f;

    uint4 a0v = *(const uint4*)Ap;
    uint4 a1v = *(const uint4*)(Ap + 8);
    uint4 b0v = *(const uint4*)Bp;
    uint4 b1v = *(const uint4*)(Bp + 8);
    *(uint4*)&As[0][lr][lc]     = a0v;
    *(uint4*)&As[0][lr][lc + 8] = a1v;
    *(uint4*)&Bs[0][lr][lc]     = b0v;
    *(uint4*)&Bs[0][lr][lc + 8] = b1v;

    const int nk = K >> 5;
    int buf = 0;
    for (int kt = 0; kt < nk; ++kt){
        __syncthreads();
        const bool more = (kt + 1) < nk;
        if (more){
            const int kk = (kt + 1) << 5;
            a0v = *(const uint4*)(Ap + kk);
            a1v = *(const uint4*)(Ap + kk + 8);
            b0v = *(const uint4*)(Bp + kk);
            b1v = *(const uint4*)(Bp + kk + 8);
        }
#pragma unroll
        for (int ks = 0; ks < 32; ks += 16){
            uint32_t af[2][4];
#pragma unroll
            for (int mi = 0; mi < 2; mi++)
                ldsm4(af[mi][0],af[mi][1],af[mi][2],af[mi][3],
                      smem_addr(&As[buf][wm*32 + mi*16 + (lane & 15)][ks + ((lane >> 4) << 3)]));
            uint32_t bq[4][4];
#pragma unroll
            for (int nq = 0; nq < 4; nq++)
                ldsm4(bq[nq][0],bq[nq][1],bq[nq][2],bq[nq][3],
                      smem_addr(&Bs[buf][wn*64 + nq*16 + ((lane >> 4) << 3) + (lane & 7)]
                                        [ks + (((lane >> 3) & 1) << 3)]));
#pragma unroll
            for (int mi = 0; mi < 2; mi++)
#pragma unroll
                for (int nq = 0; nq < 4; nq++){
                    mma_bf16(acc[mi][nq*2],   af[mi][0],af[mi][1],af[mi][2],af[mi][3], bq[nq][0], bq[nq][1]);
                    mma_bf16(acc[mi][nq*2+1], af[mi][0],af[mi][1],af[mi][2],af[mi][3], bq[nq][2], bq[nq][3]);
                }
        }
        if (more){
            *(uint4*)&As[buf^1][lr][lc]     = a0v;
            *(uint4*)&As[buf^1][lr][lc + 8] = a1v;
            *(uint4*)&Bs[buf^1][lr][lc]     = b0v;
            *(uint4*)&Bs[buf^1][lr][lc + 8] = b1v;
        }
        buf ^= 1;
    }

#pragma unroll
    for (int mi = 0; mi < 2; mi++)
#pragma unroll
        for (int ni = 0; ni < 8; ni++)
#pragma unroll
            for (int e = 0; e < 4; e++){
                int r = m0 + wm*32 + mi*16 + (lane >> 2) + ((e >> 1) << 3);
                int c = n0 + wn*64 + ni*8 + ((lane & 3) << 1) + (e & 1);
                if (r < M)
                    Cf[(long)r * ldc + c] = acc[mi][ni][e];
            }
}

// ---------------- merged fp32->bf16 conversion ----------------
struct CvtArgs {
    const float4* s[7];
    __nv_bfloat162* d[7];
    int cum[8];
};
__global__ void cvt_all_kernel(CvtArgs a){
    int tot = a.cum[7];
    for (int i = blockIdx.x * blockDim.x + threadIdx.x; i < tot; i += gridDim.x * blockDim.x){
        int s = 0;
#pragma unroll
        for (int j = 1; j < 7; j++) s += (i >= a.cum[j]);
        int loc = i - a.cum[s];
        float4 v = a.s[s][loc];
        a.d[s][2*loc]   = __floats2bfloat162_rn(v.x, v.y);
        a.d[s][2*loc+1] = __floats2bfloat162_rn(v.z, v.w);
    }
}

// ---------------- small prework kernels ----------------
__global__ void reset_kernel(void){
    int i = threadIdx.x;
    if (i < 4*32) g_ctr[i] = 0u;
    if (i == 0) g_witem = 0u;
}
__global__ void build_idx_kernel(const int* __restrict__ x, int* __restrict__ idx){
    int i = blockIdx.x * blockDim.x + threadIdx.x;
    if (i < TT * BB) {
        int t = i >> 8, b = i & 255;
        idx[i] = x[b * TT + t];
    }
}
__global__ void split_init_kernel(const float* __restrict__ hh, bf16* __restrict__ hdst,
                                  float* __restrict__ c){
    int i = blockIdx.x * blockDim.x + threadIdx.x;
    if (i >= BB * DD) return;
    int b = i >> 9, d = i & 511;
    hdst[b * 512 + d] = __float2bfloat16(hh[b * 1024 + d]);
    c[i] = hh[b * 1024 + 512 + d];
}

// ---------------- persistent recurrence kernel (cp.async 4-stage ring, K64) ----------------
__device__ __forceinline__ void gsync_group(int g, unsigned target){
    __threadfence();
    __syncthreads();
    if (threadIdx.x == 0){
        atomicAdd(&g_ctr[g*32], 1u);
        volatile unsigned* p = &g_ctr[g*32];
        while (*p < target) __nanosleep(32);
        __threadfence();
    }
    __syncthreads();
}

__device__ __forceinline__ void cell_item(
    bf16 (*As)[72], bf16 (*Bs)[72], int mt, int dt,
    const bf16* __restrict__ A1, const bf16* __restrict__ A2, int Ktot,
    const bf16* __restrict__ W, int ldb,
    const float* __restrict__ add, int addStride,
    const int* __restrict__ idx2,
    const float* __restrict__ add2,
    float* __restrict__ cst,
    bf16* __restrict__ hdst,
    const bf16* __restrict__ h0new,
    bf16* __restrict__ Hout)
{
    const int tid = threadIdx.x;
    const int lane = tid & 31, warp = tid >> 5;
    const int wm = warp >> 1, wn = warp & 1;
    const int lrow = tid >> 2;
    const int lseg = (tid & 3) << 4;
    const int r_glob = mt*64 + lrow;
    const bf16* Arow1 = A1 + (size_t)r_glob*512;
    const bf16* Arow2 = A2 + (size_t)r_glob*512;
    const bf16* Bp = W + (size_t)((lrow >> 4) * 512 + dt*16 + (lrow & 15)) * ldb;

    float acc[4][4];
#pragma unroll
    for (int g = 0; g < 4; g++)
#pragma unroll
        for (int e = 0; e < 4; e++) acc[g][e] = 0.f;

    const int nk = Ktot >> 6;

    auto issue = [&](int kt){
        const int kk = kt << 6;
        const int sb = (kt & 3) * 64;
#pragma unroll
        for (int j = 0; j < 2; j++){
            const int c = kk + lseg + j*8;
            const bf16* ap = (c < 512) ? (Arow1 + c) : (Arow2 + c - 512);
            cpa16(smem_addr(&As[sb + lrow][lseg + j*8]), ap);
            cpa16(smem_addr(&Bs[sb + lrow][lseg + j*8]), Bp + c);
        }
    };

    issue(0); cpa_commit();
    issue(1); cpa_commit();
    issue(2); cpa_commit();

    for (int kt = 0; kt < nk; ++kt){
        cpa_wait2();
        __syncthreads();
        if (kt + 3 < nk) issue(kt + 3);
        cpa_commit();
        const int sb = (kt & 3) * 64;
#pragma unroll
        for (int ks = 0; ks < 64; ks += 16){
            uint32_t a0,a1,a2,a3;
            ldsm4(a0,a1,a2,a3,
                  smem_addr(&As[sb + wm*16 + (lane & 15)][ks + ((lane >> 4) << 3)]));
            uint32_t bq[8];
#pragma unroll
            for (int gp = 0; gp < 2; gp++)
                ldsm4(bq[gp*4+0], bq[gp*4+1], bq[gp*4+2], bq[gp*4+3],
                      smem_addr(&Bs[sb + gp*32 + ((lane >> 4) << 4) + wn*8 + (lane & 7)]
                                   [ks + (((lane >> 3) & 1) << 3)]));
#pragma unroll
            for (int g = 0; g < 4; g++)
                mma_bf16(acc[g], a0,a1,a2,a3, bq[g*2], bq[g*2+1]);
        }
    }

    const int rb0 = mt*64 + wm*16 + (lane >> 2);
    const int cc  = dt*16 + wn*8 + ((lane & 3) << 1);
    int sel0 = idx2 ? idx2[rb0]     : rb0;
    int sel1 = idx2 ? idx2[rb0 + 8] : (rb0 + 8);
#pragma unroll
    for (int e = 0; e < 4; e++){
        int r = rb0 + ((e >> 1) << 3);
        int c = cc + (e & 1);
        const float* ar = add + (size_t)((e >> 1) ? sel1 : sel0) * addStride;
        float p0 = acc[0][e] + ar[c];
        float p1 = acc[1][e] + ar[512 + c];
        float p2 = acc[2][e] + ar[1024 + c];
        float p3 = acc[3][e] + ar[1536 + c];
        if (add2){
            const float* a2r = add2 + (size_t)r * 2048;
            p0 += a2r[c]; p1 += a2r[512 + c]; p2 += a2r[1024 + c]; p3 += a2r[1536 + c];
        }
        float ig = sigfast(p0), fg = sigfast(p1), og = sigfast(p2);
        float cn = tanhfast(p3);
        size_t idx = (size_t)r*512 + c;
        float cnew = fg * cst[idx] + ig * cn;
        cst[idx] = cnew;
        float h = og * tanhfast(cnew);
        hdst[idx] = __float2bfloat16(h);
        if (Hout)
            Hout[idx] = __float2bfloat16(h + __bfloat162float(h0new[idx]));
    }
}

#define LOOP_SMEM (2 * 256 * 72 * 2)   // As + Bs, [4*64][72] bf16 each

__global__ void __launch_bounds__(256, 2)
loop_kernel(const float* __restrict__ bg1)
{
    extern __shared__ bf16 dsm_loop[];
    bf16 (*As)[72] = (bf16(*)[72])dsm_loop;
    bf16 (*Bs)[72] = (bf16(*)[72])(dsm_loop + 256*72);

    const int bid = blockIdx.x;
    const bool isC1 = (bid < 128);
    const bool isC0 = (bid >= 148 && bid < 276);
    if (!isC1 && !isC0) return;
    const int it = isC1 ? bid : (bid - 148);
    const int mt = it >> 5, dt = it & 31;

    for (int p = 0; p < 40; p++){
        const int rb = p & 1, wb = rb ^ 1;
        if (isC1 && p >= 1){
            cell_item(As, Bs, mt, dt, s_h1d[wb], s_h0d[rb], 1024, s_Wg1b, 1024,
                      bg1, 0, nullptr, nullptr,
                      s_c1, s_h1d[rb], s_h0d[rb],
                      s_Hall + (size_t)(p-1)*256*512);
        } else if (isC0 && p <= 38){
            cell_item(As, Bs, mt, dt, s_h0d[rb], s_h0d[rb], 512, s_Wg0b, 1152,
                      s_embW, 2048, s_idx + p*256, s_gz0,
                      s_c0, s_h0d[wb], nullptr, nullptr);
        }
        gsync_group(mt, 64u * (unsigned)(p + 1));
    }
}

// ---------------- fused logits + log-softmax (K=512, zlog addend) --------------
#define LG_KP  520
#define LG_KST 16
#define LG_NT  40
#define LG_SMEM (64*LG_KP*2 + 2*128*40*2 + 2*64*8*4)

__global__ void __launch_bounds__(256, 2)
logits_lse_kernel(const int* __restrict__ x, float* __restrict__ lp)
{
    extern __shared__ char dsm[];
    bf16 (*As)[LG_KP]    = (bf16(*)[LG_KP])dsm;
    bf16 (*Bs)[128][40]  = (bf16(*)[128][40])(dsm + 64*LG_KP*2);
    float* s_red = (float*)(dsm + 64*LG_KP*2 + 2*128*40*2);  // [64][8]
    float* t_red = s_red + 64*8;

    const int tid = threadIdx.x, lane = tid & 31, warp = tid >> 5;
    const int rb = blockIdx.x;
    const int t  = rb >> 2;
    const int r0 = rb * 64;

    // resident A: rows [r0, r0+64) = Hall rows (K=512)
    {
        int row = tid >> 2, q0 = tid & 3;
        const bf16* hr = s_Hall + (size_t)(r0 + row) * 512;
        for (int q = q0; q < 64; q += 4){
            int col = q * 8;
            *(uint4*)&As[row][col] = *(const uint4*)(hr + col);
        }
    }

    int xi8[8], b8[8];
    float sr[8], tv[8];
#pragma unroll
    for (int i = 0; i < 8; i++){ sr[i] = 0.f; tv[i] = 0.f; }
#pragma unroll
    for (int mi = 0; mi < 4; mi++)
#pragma unroll
        for (int hh = 0; hh < 2; hh++){
            int rloc = mi*16 + (lane >> 2) + hh*8;
            int b = (r0 + rloc) & 255;
            b8[mi*2+hh] = b;
            xi8[mi*2+hh] = __ldg(x + b*TT + t + 1);
        }

    float acc[4][2][4];
#pragma unroll
    for (int mi=0;mi<4;mi++)
#pragma unroll
        for(int ni=0;ni<2;ni++)
#pragma unroll
            for(int e=0;e<4;e++) acc[mi][ni][e]=0.f;

    const int brow0 = tid >> 2, bseg = (tid & 3) << 3;
    const uint4 z4 = make_uint4(0u,0u,0u,0u);

    uint4 bv0, bv1;
    {
        int nr0 = brow0, nr1 = brow0 + 64;
        bv0 = (nr0 < VV) ? *(const uint4*)(s_Woutb + (size_t)nr0*640 + bseg) : z4;
        bv1 = (nr1 < VV) ? *(const uint4*)(s_Woutb + (size_t)nr1*640 + bseg) : z4;
    }
    *(uint4*)&Bs[0][brow0][bseg]      = bv0;
    *(uint4*)&Bs[0][brow0 + 64][bseg] = bv1;

    const int NST = LG_NT * LG_KST;
    for (int gs = 0; gs < NST; gs++){
        __syncthreads();
        const int buf = gs & 1;
        const bool more = (gs + 1) < NST;
        if (more){
            int g2 = gs + 1;
            int nt2 = g2 / LG_KST, kst2 = g2 % LG_KST;
            int nr0 = nt2*128 + brow0, nr1 = nr0 + 64;
            int kc = kst2 * 32;
            bv0 = (nr0 < VV) ? *(const uint4*)(s_Woutb + (size_t)nr0*640 + kc + bseg) : z4;
            bv1 = (nr1 < VV) ? *(const uint4*)(s_Woutb + (size_t)nr1*640 + kc + bseg) : z4;
        }
        const int kst = gs % LG_KST;
        const int kbase = kst * 32;
#pragma unroll
        for (int ks = 0; ks < 32; ks += 16){
            uint32_t af[4][4];
#pragma unroll
            for (int mi = 0; mi < 4; mi++)
                ldsm4(af[mi][0],af[mi][1],af[mi][2],af[mi][3],
                      smem_addr(&As[mi*16 + (lane & 15)][kbase + ks + ((lane >> 4) << 3)]));
            uint32_t bq[4];
            ldsm4(bq[0],bq[1],bq[2],bq[3],
                  smem_addr(&Bs[buf][warp*16 + ((lane >> 4) << 3) + (lane & 7)]
                                    [ks + (((lane >> 3) & 1) << 3)]));
#pragma unroll
            for (int mi = 0; mi < 4; mi++){
                mma_bf16(acc[mi][0], af[mi][0],af[mi][1],af[mi][2],af[mi][3], bq[0], bq[1]);
                mma_bf16(acc[mi][1], af[mi][0],af[mi][1],af[mi][2],af[mi][3], bq[2], bq[3]);
            }
        }
        if (more){
            *(uint4*)&Bs[buf^1][brow0][bseg]      = bv0;
            *(uint4*)&Bs[buf^1][brow0 + 64][bseg] = bv1;
        }
        if (kst == LG_KST - 1){
            int nt = gs / LG_KST;
            int cb = nt*128 + warp*16 + ((lane & 3) << 1);
#pragma unroll
            for (int ni = 0; ni < 2; ni++)
#pragma unroll
                for (int e2 = 0; e2 < 2; e2++){
                    int c = cb + ni*8 + e2;
                    if (c < VV){
#pragma unroll
                        for (int mi = 0; mi < 4; mi++)
#pragma unroll
                            for (int hh = 0; hh < 2; hh++){
                                float v = acc[mi][ni][hh*2 + e2]
                                        + __ldg(s_zlog + (size_t)b8[mi*2+hh]*VV + c);
                                sr[mi*2+hh] += __expf(v - 8.f);
                                if (c == xi8[mi*2+hh]) tv[mi*2+hh] = v;
                            }
                    }
                }
#pragma unroll
            for (int mi=0;mi<4;mi++)
#pragma unroll
                for(int ni=0;ni<2;ni++)
#pragma unroll
                    for(int e=0;e<4;e++) acc[mi][ni][e]=0.f;
        }
    }

#pragma unroll
    for (int i = 0; i < 8; i++){
        sr[i] += __shfl_xor_sync(0xffffffffu, sr[i], 1);
        sr[i] += __shfl_xor_sync(0xffffffffu, sr[i], 2);
        tv[i] += __shfl_xor_sync(0xffffffffu, tv[i], 1);
        tv[i] += __shfl_xor_sync(0xffffffffu, tv[i], 2);
    }
    if ((lane & 3) == 0){
        int q = lane >> 2;
#pragma unroll
        for (int mi = 0; mi < 4; mi++)
#pragma unroll
            for (int hh = 0; hh < 2; hh++){
                int rloc = mi*16 + q + hh*8;
                s_red[rloc*8 + warp] = sr[mi*2+hh];
                t_red[rloc*8 + warp] = tv[mi*2+hh];
            }
    }
    __syncthreads();
    if (tid < 64){
        float S = 0.f, T = 0.f;
#pragma unroll
        for (int w = 0; w < 8; w++){ S += s_red[tid*8 + w]; T += t_red[tid*8 + w]; }
        lp[(size_t)t*256 + ((r0 + tid) & 255)] = T - (8.f + logf(S));
    }
}

__global__ void lp_sum_kernel(const float* __restrict__ lp, float* __restrict__ out){
    int b = threadIdx.x;
    float a = 0.f;
    for (int t = 0; t < 39; t++) a += lp[t*256 + b];
    out[b] = a;
}

// ---------------- host side ----------------
enum { OP_NONE = 0, OP_RELU = 1, OP_TANH = 2 };

static inline void G(int M, int N, int K,
                     const void* A, int lda, const int* aidx,
                     const void* B, int ldb,
                     const float* bias,
                     const float* D, int ldd, int dmask,
                     float* Cf, void* Cb, int ldc, int op)
{
    dim3 grid((N + 63) / 64, (M + 63) / 64);
    gemm_kernel<<<grid, 128>>>(M, N, K,
        (const bf16*)A, lda, aidx,
        (const bf16*)B, ldb, bias, D, ldd, dmask,
        Cf, (bf16*)Cb, ldc, op);
}

extern "C" void kernel_launch(void* const* d_in, const int* in_sizes, int n_in,
                              void* d_out, int out_size)
{
    const float* z    = (const float*)d_in[0];
    const int*   x    = (const int*)  d_in[1];
    const float* emb  = (const float*)d_in[2];
    const float* Wg0  = (const float*)d_in[3];
    const float* bg0  = (const float*)d_in[4];
    const float* Wg1  = (const float*)d_in[5];
    const float* bg1  = (const float*)d_in[6];
    const float* Wout = (const float*)d_in[7];
    const float* bout = (const float*)d_in[8];
    const float* tw1  = (const float*)d_in[9];
    const float* tb1  = (const float*)d_in[10];
    const float* tw2  = (const float*)d_in[11];
    const float* tb2  = (const float*)d_in[12];
    float* out = (float*)d_out;

    void* q;
#define GET(ptr, sym, type) type* ptr; do { cudaGetSymbolAddress(&q, sym); ptr = (type*)q; } while (0)
    GET(p_Wg0b, s_Wg0b, bf16);
    GET(p_Wg1b, s_Wg1b, bf16);
    GET(p_Woutb, s_Woutb, bf16);
    GET(p_tw1b, s_tw1b, bf16);
    GET(p_tw2b, s_tw2b, bf16);
    GET(p_embb, s_embb, bf16);
    GET(p_zb,  s_zb,  bf16);
    GET(p_h0d, s_h0d, bf16);
    GET(p_h1d, s_h1d, bf16);
    GET(p_r,   s_r,   bf16);
    GET(p_c0,  s_c0,  float);
    GET(p_c1,  s_c1,  float);
    GET(p_gz0, s_gz0, float);
    GET(p_hh,  s_hh,  float);
    GET(p_embW, s_embW, float);
    GET(p_zlog, s_zlog, float);
    GET(p_lp,  s_lp,  float);
    GET(p_idx, s_idx, int);
#undef GET

    // merged fp32->bf16 conversion (single kernel)
    {
        CvtArgs a;
        const float* srcs[7] = {z, emb, Wg0, Wg1, Wout, tw1, tw2};
        bf16* dsts[7] = {p_zb, p_embb, p_Wg0b, p_Wg1b, p_Woutb, p_tw1b, p_tw2b};
        int n4s[7] = {BB*ZZ/4, VV*DD/4, 4*512*1152/4, 4*512*1024/4, VV*640/4,
                      2*2048*128/4, 2*1024*2048/4};
        int cum = 0;
        for (int j = 0; j < 7; j++){
            a.s[j] = (const float4*)srcs[j];
            a.d[j] = (__nv_bfloat162*)dsts[j];
            a.cum[j] = cum;
            cum += n4s[j];
        }
        a.cum[7] = cum;
        cvt_all_kernel<<<592, 256>>>(a);
    }

    reset_kernel<<<1, 128>>>();
    build_idx_kernel<<<(TT * BB + 255) / 256, 256>>>(x, p_idx);

    // init states: hh = tanh(relu(z @ tw1^T + tb1) @ tw2^T + tb2) -> (h, c)
    for (int l = 0; l < 2; l++) {
        G(256, 2048, 128, p_zb, 128, nullptr,
          p_tw1b + (size_t)l * 2048 * 128, 128, tb1 + l * 2048,
          nullptr, 0, 0, nullptr, p_r, 2048, OP_RELU);
        G(256, 1024, 2048, p_r, 2048, nullptr,
          p_tw2b + (size_t)l * 1024 * 2048, 2048, tb2 + l * 1024,
          nullptr, 0, 0, p_hh, nullptr, 1024, OP_TANH);
        if (l == 0) split_init_kernel<<<512, 256>>>(p_hh, p_h0d, p_c0);
        else        split_init_kernel<<<512, 256>>>(p_hh, p_h1d, p_c1);
    }

    // gz0 = z @ W0z^T + bg0
    G(256, 2048, 128, p_zb, 128, nullptr, p_Wg0b + 1024, 1152, bg0,
      nullptr, 0, 0, p_gz0, nullptr, 2048, OP_NONE);

    // zlog = z @ WoutZ^T + bout  (removes z from logits K)
    G(256, 5000, 128, p_zb, 128, nullptr, p_Woutb + 512, 640, bout,
      nullptr, 0, 0, p_zlog, nullptr, 5000, OP_NONE);

    // embW = emb @ W0e^T for ALL vocab rows (5000 x 2048)
    {
        dim3 grid(2048 / 128, (VV + 127) / 128);
        gemm128_kernel<<<grid, 256>>>(VV, 2048, 512,
            p_embb, 512, p_Wg0b + 512, 1152, p_embW, 2048);
    }

    // recurrence only (cells), per-row-block group barriers, H(t) archived
    cudaFuncSetAttribute(loop_kernel,
                         cudaFuncAttributeMaxDynamicSharedMemorySize, LOOP_SMEM);
    loop_kernel<<<NBLK, 256, LOOP_SMEM>>>(bg1);

    // fused logits + log-softmax over all 39 steps (K=512, zlog addend)
    cudaFuncSetAttribute(logits_lse_kernel,
                         cudaFuncAttributeMaxDynamicSharedMemorySize, LG_SMEM);
    logits_lse_kernel<<<156, 256, LG_SMEM>>>(x, p_lp);

    // deterministic per-b sum over t
    lp_sum_kernel<<<1, 256>>>(p_lp, out);

    (void)in_sizes; (void)n_in; (void)out_size;
}

// round 16
// speedup vs baseline: 1.1631x; 1.1631x over previous
#include <cuda_runtime.h>
#include <cuda_bf16.h>
#include <math.h>
#include <stdint.h>

typedef __nv_bfloat16 bf16;

#define BB 256
#define TT 40
#define VV 5000
#define DD 512
#define ZZ 128
#define NBLK 276   // 128 cell1 + 20 idle + 128 cell0

// ---------------- device scratch (static; no allocation) ----------------
__device__ bf16 s_Wg0b[4*512*1152];
__device__ bf16 s_Wg1b[4*512*1024];
__device__ bf16 s_Woutb[5000*640];
__device__ bf16 s_tw1b[2*2048*128];
__device__ bf16 s_tw2b[2*1024*2048];
__device__ bf16 s_embb[5000*512];
__device__ bf16 s_zb[256*128];
__device__ bf16 s_h0d[2][256*512];
__device__ bf16 s_h1d[2][256*512];
__device__ bf16 s_Hall[39*256*512];      // H(t) for t=0..38
__device__ bf16 s_r[256*2048];
__device__ float s_c0[256*512];
__device__ float s_c1[256*512];
__device__ float s_gz0[256*2048];
__device__ float s_hh[256*1024];
__device__ float s_embW[5000*2048];      // emb @ W0e^T  (vocab-level, fp32)
__device__ float s_zlog[256*5000];       // z @ WoutZ^T + bout
__device__ float s_lgS[8*39*256];        // per vocab-octant partial sum-exp
__device__ float s_lgT[8*39*256];        // per vocab-octant target logit
__device__ int   s_idx[40*256];
__device__ unsigned g_ctr[4*32];         // per-row-block monotonic barrier counters
__device__ unsigned g_witem;

// ---------------- mma / async helpers ----------------
__device__ __forceinline__ unsigned smem_addr(const void* p){
    return (unsigned)__cvta_generic_to_shared(p);
}
__device__ __forceinline__ void ldsm4(uint32_t& r0, uint32_t& r1, uint32_t& r2, uint32_t& r3, unsigned a){
    asm volatile("ldmatrix.sync.aligned.m8n8.x4.shared.b16 {%0,%1,%2,%3}, [%4];"
                 : "=r"(r0),"=r"(r1),"=r"(r2),"=r"(r3) : "r"(a));
}
__device__ __forceinline__ void ldsm2(uint32_t& r0, uint32_t& r1, unsigned a){
    asm volatile("ldmatrix.sync.aligned.m8n8.x2.shared.b16 {%0,%1}, [%2];"
                 : "=r"(r0),"=r"(r1) : "r"(a));
}
__device__ __forceinline__ void mma_bf16(float c[4], uint32_t a0,uint32_t a1,uint32_t a2,uint32_t a3,
                                         uint32_t b0,uint32_t b1){
    asm volatile("mma.sync.aligned.m16n8k16.row.col.f32.bf16.bf16.f32 "
                 "{%0,%1,%2,%3}, {%4,%5,%6,%7}, {%8,%9}, {%0,%1,%2,%3};"
                 : "+f"(c[0]),"+f"(c[1]),"+f"(c[2]),"+f"(c[3])
                 : "r"(a0),"r"(a1),"r"(a2),"r"(a3),"r"(b0),"r"(b1));
}
__device__ __forceinline__ void cpa16(unsigned dst, const void* src){
    asm volatile("cp.async.cg.shared.global [%0], [%1], 16;" :: "r"(dst), "l"(src));
}
__device__ __forceinline__ void cpa_commit(){ asm volatile("cp.async.commit_group;"); }
__device__ __forceinline__ void cpa_wait1(){ asm volatile("cp.async.wait_group 1;"); }
__device__ __forceinline__ float sigf(float x){ return 1.f / (1.f + __expf(-x)); }

// ---------------- generic bf16 TN GEMM (64x64, prework/small) ----------------
__global__ __launch_bounds__(128)
void gemm_kernel(int M, int N, int K,
                 const bf16* __restrict__ A, int lda, const int* __restrict__ aidx,
                 const bf16* __restrict__ B, int ldb,
                 const float* __restrict__ bias,
                 const float* __restrict__ Dadd, int ldd, int dmask,
                 float* __restrict__ Cf, bf16* __restrict__ Cb, int ldc, int op)
{
    __shared__ bf16 As[2][64][40];
    __shared__ bf16 Bs[2][64][40];
    const int t  = threadIdx.x;
    const int m0 = blockIdx.y << 6, n0 = blockIdx.x << 6;
    const int ar0 = t >> 2;
    const int ak0 = (t & 3) << 3;

    long arow0 = aidx ? (long)aidx[m0 + ar0]      : (long)(m0 + ar0);
    long arow1 = aidx ? (long)aidx[m0 + ar0 + 32] : (long)(m0 + ar0 + 32);
    const bf16* Ap0 = A + arow0 * lda + ak0;
    const bf16* Ap1 = A + arow1 * lda + ak0;
    const bool bv0 = (n0 + ar0)      < N;
    const bool bv1 = (n0 + ar0 + 32) < N;
    const bf16* Bp0 = B + (long)(n0 + ar0)      * ldb + ak0;
    const bf16* Bp1 = B + (long)(n0 + ar0 + 32) * ldb + ak0;

    const int warp = t >> 5, lane = t & 31;
    const int wm = (warp >> 1) << 5, wn = (warp & 1) << 5;
    const int a_mr = lane & 15, a_kf = (lane >> 4) << 3;
    const int b_nr = lane & 7,  b_kf = ((lane >> 3) & 1) << 3;

    float acc[2][4][4];
#pragma unroll
    for (int i = 0; i < 2; i++)
#pragma unroll
        for (int j = 0; j < 4; j++)
#pragma unroll
            for (int e = 0; e < 4; e++) acc[i][j][e] = 0.f;

    const uint4 z4 = make_uint4(0u,0u,0u,0u);
    uint4 av0 = *(const uint4*)Ap0;
    uint4 av1 = *(const uint4*)Ap1;
    uint4 bw0 = bv0 ? *(const uint4*)Bp0 : z4;
    uint4 bw1 = bv1 ? *(const uint4*)Bp1 : z4;
    *(uint4*)&As[0][ar0][ak0]      = av0;
    *(uint4*)&As[0][ar0 + 32][ak0] = av1;
    *(uint4*)&Bs[0][ar0][ak0]      = bw0;
    *(uint4*)&Bs[0][ar0 + 32][ak0] = bw1;

    const int nk = K >> 5;
    int buf = 0;
    for (int kt = 0; kt < nk; ++kt) {
        __syncthreads();
        const bool more = (kt + 1) < nk;
        if (more) {
            const int kk = (kt + 1) << 5;
            av0 = *(const uint4*)(Ap0 + kk);
            av1 = *(const uint4*)(Ap1 + kk);
            bw0 = bv0 ? *(const uint4*)(Bp0 + kk) : z4;
            bw1 = bv1 ? *(const uint4*)(Bp1 + kk) : z4;
        }
#pragma unroll
        for (int ks = 0; ks < 32; ks += 16) {
            uint32_t af[2][4], bfr[4][2];
#pragma unroll
            for (int mi = 0; mi < 2; mi++)
                ldsm4(af[mi][0], af[mi][1], af[mi][2], af[mi][3],
                      smem_addr(&As[buf][wm + mi*16 + a_mr][ks + a_kf]));
#pragma unroll
            for (int ni = 0; ni < 4; ni++)
                ldsm2(bfr[ni][0], bfr[ni][1],
                      smem_addr(&Bs[buf][wn + ni*8 + b_nr][ks + b_kf]));
#pragma unroll
            for (int mi = 0; mi < 2; mi++)
#pragma unroll
                for (int ni = 0; ni < 4; ni++)
                    mma_bf16(acc[mi][ni], af[mi][0], af[mi][1], af[mi][2], af[mi][3],
                             bfr[ni][0], bfr[ni][1]);
        }
        if (more) {
            *(uint4*)&As[buf^1][ar0][ak0]      = av0;
            *(uint4*)&As[buf^1][ar0 + 32][ak0] = av1;
            *(uint4*)&Bs[buf^1][ar0][ak0]      = bw0;
            *(uint4*)&Bs[buf^1][ar0 + 32][ak0] = bw1;
        }
        buf ^= 1;
    }

    const int rbase = m0 + wm + (lane >> 2);
    const int cbase = n0 + wn + ((lane & 3) << 1);
#pragma unroll
    for (int mi = 0; mi < 2; mi++)
#pragma unroll
        for (int ni = 0; ni < 4; ni++)
#pragma unroll
            for (int e = 0; e < 4; e++) {
                int r = rbase + mi*16 + (e >> 1) * 8;
                int c = cbase + ni*8 + (e & 1);
                if (c < N) {
                    float v = acc[mi][ni][e];
                    if (bias) v += __ldg(bias + c);
                    if (Dadd) v += Dadd[(long)(r & dmask) * ldd + c];
                    if (op == 1) v = fmaxf(v, 0.f);
                    else if (op == 2) v = tanhf(v);
                    if (Cf) Cf[(long)r * ldc + c] = v;
                    if (Cb) Cb[(long)r * ldc + c] = __float2bfloat16(v);
                }
            }
}

// ---------------- big 128x128-tile GEMM: C = A*B^T (M-guarded) ----------------
__global__ __launch_bounds__(256)
void gemm128_kernel(int M, int N, int K,
                    const bf16* __restrict__ A, int lda,
                    const bf16* __restrict__ B, int ldb,
                    float* __restrict__ Cf, int ldc)
{
    __shared__ bf16 As[2][128][40];
    __shared__ bf16 Bs[2][128][40];
    const int t  = threadIdx.x;
    const int m0 = blockIdx.y << 7, n0 = blockIdx.x << 7;
    const int lr = t >> 1;
    const int lc = (t & 1) << 4;

    int arow = m0 + lr; if (arow >= M) arow = M - 1;
    const bf16* Ap = A + (long)arow * lda + lc;
    const bf16* Bp = B + (long)(n0 + lr) * ldb + lc;

    const int warp = t >> 5, lane = t & 31;
    const int wm = warp & 3, wn = warp >> 2;

    float acc[2][8][4];
#pragma unroll
    for (int mi = 0; mi < 2; mi++)
#pragma unroll
        for (int ni = 0; ni < 8; ni++)
#pragma unroll
            for (int e = 0; e < 4; e++) acc[mi][ni][e] = 0.f;

    uint4 a0v = *(const uint4*)Ap;
    uint4 a1v = *(const uint4*)(Ap + 8);
    uint4 b0v = *(const uint4*)Bp;
    uint4 b1v = *(const uint4*)(Bp + 8);
    *(uint4*)&As[0][lr][lc]     = a0v;
    *(uint4*)&As[0][lr][lc + 8] = a1v;
    *(uint4*)&Bs[0][lr][lc]     = b0v;
    *(uint4*)&Bs[0][lr][lc + 8] = b1v;

    const int nk = K >> 5;
    int buf = 0;
    for (int kt = 0; kt < nk; ++kt){
        __syncthreads();
        const bool more = (kt + 1) < nk;
        if (more){
            const int kk = (kt + 1) << 5;
            a0v = *(const uint4*)(Ap + kk);
            a1v = *(const uint4*)(Ap + kk + 8);
            b0v = *(const uint4*)(Bp + kk);
            b1v = *(const uint4*)(Bp + kk + 8);
        }
#pragma unroll
        for (int ks = 0; ks < 32; ks += 16){
            uint32_t af[2][4];
#pragma unroll
            for (int mi = 0; mi < 2; mi++)
                ldsm4(af[mi][0],af[mi][1],af[mi][2],af[mi][3],
                      smem_addr(&As[buf][wm*32 + mi*16 + (lane & 15)][ks + ((lane >> 4) << 3)]));
            uint32_t bq[4][4];
#pragma unroll
            for (int nq = 0; nq < 4; nq++)
                ldsm4(bq[nq][0],bq[nq][1],bq[nq][2],bq[nq][3],
                      smem_addr(&Bs[buf][wn*64 + nq*16 + ((lane >> 4) << 3) + (lane & 7)]
                                        [ks + (((lane >> 3) & 1) << 3)]));
#pragma unroll
            for (int mi = 0; mi < 2; mi++)
#pragma unroll
                for (int nq = 0; nq < 4; nq++){
                    mma_bf16(acc[mi][nq*2],   af[mi][0],af[mi][1],af[mi][2],af[mi][3], bq[nq][0], bq[nq][1]);
                    mma_bf16(acc[mi][nq*2+1], af[mi][0],af[mi][1],af[mi][2],af[mi][3], bq[nq][2], bq[nq][3]);
                }
        }
        if (more){
            *(uint4*)&As[buf^1][lr][lc]     = a0v;
            *(uint4*)&As[buf^1][lr][lc + 8] = a1v;
            *(uint4*)&Bs[buf^1][lr][lc]     = b0v;
            *(uint4*)&Bs[buf^1][lr][lc + 8] = b1v;
        }
        buf ^= 1;
    }

#pragma unroll
    for (int mi = 0; mi < 2; mi++)
#pragma unroll
        for (int ni = 0; ni < 8; ni++)
#pragma unroll
            for (int e = 0; e < 4; e++){
                int r = m0 + wm*32 + mi*16 + (lane >> 2) + ((e >> 1) << 3);
                int c = n0 + wn*64 + ni*8 + ((lane & 3) << 1) + (e & 1);
                if (r < M)
                    Cf[(long)r * ldc + c] = acc[mi][ni][e];
            }
}

// ---------------- merged fp32->bf16 conversion ----------------
struct CvtArgs {
    const float4* s[7];
    __nv_bfloat162* d[7];
    int cum[8];
};
__global__ void cvt_all_kernel(CvtArgs a){
    int tot = a.cum[7];
    for (int i = blockIdx.x * blockDim.x + threadIdx.x; i < tot; i += gridDim.x * blockDim.x){
        int s = 0;
#pragma unroll
        for (int j = 1; j < 7; j++) s += (i >= a.cum[j]);
        int loc = i - a.cum[s];
        float4 v = a.s[s][loc];
        a.d[s][2*loc]   = __floats2bfloat162_rn(v.x, v.y);
        a.d[s][2*loc+1] = __floats2bfloat162_rn(v.z, v.w);
    }
}

// ---------------- small prework kernels ----------------
__global__ void reset_kernel(void){
    int i = threadIdx.x;
    if (i < 4*32) g_ctr[i] = 0u;
    if (i == 0) g_witem = 0u;
}
__global__ void build_idx_kernel(const int* __restrict__ x, int* __restrict__ idx){
    int i = blockIdx.x * blockDim.x + threadIdx.x;
    if (i < TT * BB) {
        int t = i >> 8, b = i & 255;
        idx[i] = x[b * TT + t];
    }
}
__global__ void split_init_kernel(const float* __restrict__ hh, bf16* __restrict__ hdst,
                                  float* __restrict__ c){
    int i = blockIdx.x * blockDim.x + threadIdx.x;
    if (i >= BB * DD) return;
    int b = i >> 9, d = i & 511;
    hdst[b * 512 + d] = __float2bfloat16(hh[b * 1024 + d]);
    c[i] = hh[b * 1024 + 512 + d];
}

// ---------------- persistent recurrence kernel (cp.async 3-stage ring, K64) ----------------
__device__ __forceinline__ void gsync_group(int g, unsigned target){
    __threadfence();
    __syncthreads();
    if (threadIdx.x == 0){
        atomicAdd(&g_ctr[g*32], 1u);
        volatile unsigned* p = &g_ctr[g*32];
        while (*p < target) __nanosleep(32);
        __threadfence();
    }
    __syncthreads();
}

__device__ __forceinline__ void cell_item(
    bf16 (*As)[72], bf16 (*Bs)[72], int mt, int dt,
    const bf16* __restrict__ A1, const bf16* __restrict__ A2, int Ktot,
    const bf16* __restrict__ W, int ldb,
    const float* __restrict__ add, int addStride,
    const int* __restrict__ idx2,
    const float* __restrict__ add2,
    float* __restrict__ cst,
    bf16* __restrict__ hdst,
    const bf16* __restrict__ h0new,
    bf16* __restrict__ Hout)
{
    const int tid = threadIdx.x;
    const int lane = tid & 31, warp = tid >> 5;
    const int wm = warp >> 1, wn = warp & 1;
    const int lrow = tid >> 2;
    const int lseg = (tid & 3) << 4;
    const int r_glob = mt*64 + lrow;
    const bf16* Arow1 = A1 + (size_t)r_glob*512;
    const bf16* Arow2 = A2 + (size_t)r_glob*512;
    const bf16* Bp = W + (size_t)((lrow >> 4) * 512 + dt*16 + (lrow & 15)) * ldb;

    float acc[4][4];
#pragma unroll
    for (int g = 0; g < 4; g++)
#pragma unroll
        for (int e = 0; e < 4; e++) acc[g][e] = 0.f;

    const int nk = Ktot >> 6;

    auto issue = [&](int kt){
        const int kk = kt << 6;
        const int sb = (kt % 3) * 64;
#pragma unroll
        for (int j = 0; j < 2; j++){
            const int c = kk + lseg + j*8;
            const bf16* ap = (c < 512) ? (Arow1 + c) : (Arow2 + c - 512);
            cpa16(smem_addr(&As[sb + lrow][lseg + j*8]), ap);
            cpa16(smem_addr(&Bs[sb + lrow][lseg + j*8]), Bp + c);
        }
    };

    issue(0); cpa_commit();
    issue(1); cpa_commit();

    for (int kt = 0; kt < nk; ++kt){
        cpa_wait1();
        __syncthreads();
        if (kt + 2 < nk) issue(kt + 2);
        cpa_commit();
        const int sb = (kt % 3) * 64;
#pragma unroll
        for (int ks = 0; ks < 64; ks += 16){
            uint32_t a0,a1,a2,a3;
            ldsm4(a0,a1,a2,a3,
                  smem_addr(&As[sb + wm*16 + (lane & 15)][ks + ((lane >> 4) << 3)]));
            uint32_t bq[8];
#pragma unroll
            for (int gp = 0; gp < 2; gp++)
                ldsm4(bq[gp*4+0], bq[gp*4+1], bq[gp*4+2], bq[gp*4+3],
                      smem_addr(&Bs[sb + gp*32 + ((lane >> 4) << 4) + wn*8 + (lane & 7)]
                                   [ks + (((lane >> 3) & 1) << 3)]));
#pragma unroll
            for (int g = 0; g < 4; g++)
                mma_bf16(acc[g], a0,a1,a2,a3, bq[g*2], bq[g*2+1]);
        }
    }

    const int rb0 = mt*64 + wm*16 + (lane >> 2);
    const int cc  = dt*16 + wn*8 + ((lane & 3) << 1);
    int sel0 = idx2 ? idx2[rb0]     : rb0;
    int sel1 = idx2 ? idx2[rb0 + 8] : (rb0 + 8);
#pragma unroll
    for (int e = 0; e < 4; e++){
        int r = rb0 + ((e >> 1) << 3);
        int c = cc + (e & 1);
        const float* ar = add + (size_t)((e >> 1) ? sel1 : sel0) * addStride;
        float p0 = acc[0][e] + ar[c];
        float p1 = acc[1][e] + ar[512 + c];
        float p2 = acc[2][e] + ar[1024 + c];
        float p3 = acc[3][e] + ar[1536 + c];
        if (add2){
            const float* a2r = add2 + (size_t)r * 2048;
            p0 += a2r[c]; p1 += a2r[512 + c]; p2 += a2r[1024 + c]; p3 += a2r[1536 + c];
        }
        float ig = sigf(p0), fg = sigf(p1), og = sigf(p2);
        float cn = tanhf(p3);
        size_t idx = (size_t)r*512 + c;
        float cnew = fg * cst[idx] + ig * cn;
        cst[idx] = cnew;
        float h = og * tanhf(cnew);
        hdst[idx] = __float2bfloat16(h);
        if (Hout)
            Hout[idx] = __float2bfloat16(h + __bfloat162float(h0new[idx]));
    }
}

#define LOOP_SMEM (2 * 192 * 72 * 2)

__global__ void __launch_bounds__(256, 2)
loop_kernel(const float* __restrict__ bg1)
{
    extern __shared__ bf16 dsm_loop[];
    bf16 (*As)[72] = (bf16(*)[72])dsm_loop;
    bf16 (*Bs)[72] = (bf16(*)[72])(dsm_loop + 192*72);

    const int bid = blockIdx.x;
    const bool isC1 = (bid < 128);
    const bool isC0 = (bid >= 148 && bid < 276);
    if (!isC1 && !isC0) return;
    const int it = isC1 ? bid : (bid - 148);
    const int mt = it >> 5, dt = it & 31;

    for (int p = 0; p < 40; p++){
        const int rb = p & 1, wb = rb ^ 1;
        if (isC1 && p >= 1){
            cell_item(As, Bs, mt, dt, s_h1d[wb], s_h0d[rb], 1024, s_Wg1b, 1024,
                      bg1, 0, nullptr, nullptr,
                      s_c1, s_h1d[rb], s_h0d[rb],
                      s_Hall + (size_t)(p-1)*256*512);
        } else if (isC0 && p <= 38){
            cell_item(As, Bs, mt, dt, s_h0d[rb], s_h0d[rb], 512, s_Wg0b, 1152,
                      s_embW, 2048, s_idx + p*256, s_gz0,
                      s_c0, s_h0d[wb], nullptr, nullptr);
        }
        gsync_group(mt, 64u * (unsigned)(p + 1));
    }
}

// ---------------- fused logits + log-softmax: balanced occ-2 work stealing --------------
// Item = (row-block rb 0..155, vocab octant oct 0..7 of 640 cols). 1248 items on a
// 296-CTA grid (exactly 2 CTAs per SM). Items rb-major so consecutive steals often
// reuse the resident A tile (skip refill when rb unchanged). Disjoint partial
// (sumexp, target) outputs per octant -> deterministic; merged in lp_sum.
#define LG_KP  520
#define LG_KST 16
#define LG_NTI 5          // 5 N-tiles of 128 per octant (640 cols)
#define LG_NITEM (156*8)
#define LG_SMEM (64*LG_KP*2 + 2*128*40*2 + 2*64*8*4)

__global__ void __launch_bounds__(256, 2)
logits_lse_kernel(const int* __restrict__ x,
                  float* __restrict__ lgS, float* __restrict__ lgT)
{
    extern __shared__ char dsm[];
    bf16 (*As)[LG_KP]    = (bf16(*)[LG_KP])dsm;
    bf16 (*Bs)[128][40]  = (bf16(*)[128][40])(dsm + 64*LG_KP*2);
    float* s_red = (float*)(dsm + 64*LG_KP*2 + 2*128*40*2);  // [64][8]
    float* t_red = s_red + 64*8;
    __shared__ int s_item;

    const int tid = threadIdx.x, lane = tid & 31, warp = tid >> 5;
    const int brow0 = tid >> 2, bseg = (tid & 3) << 3;
    const uint4 z4 = make_uint4(0u,0u,0u,0u);
    int last_rb = -1;

    for (;;){
        if (tid == 0) s_item = (int)atomicAdd(&g_witem, 1u);
        __syncthreads();
        const int item = s_item;
        if (item >= LG_NITEM) break;
        const int rb  = item >> 3;
        const int oct = item & 7;
        const int t   = rb >> 2;
        const int r0  = rb * 64;
        const int cof = oct * 640;

        // resident A: rows [r0, r0+64) = Hall rows (K=512); skip if same rb
        if (rb != last_rb){
            int row = tid >> 2, q0 = tid & 3;
            const bf16* hr = s_Hall + (size_t)(r0 + row) * 512;
            for (int qq = q0; qq < 64; qq += 4){
                int col = qq * 8;
                *(uint4*)&As[row][col] = *(const uint4*)(hr + col);
            }
            last_rb = rb;
        }

        int xi8[8], b8[8];
        float sr[8], tv[8];
#pragma unroll
        for (int i = 0; i < 8; i++){ sr[i] = 0.f; tv[i] = 0.f; }
#pragma unroll
        for (int mi = 0; mi < 4; mi++)
#pragma unroll
            for (int hh = 0; hh < 2; hh++){
                int rloc = mi*16 + (lane >> 2) + hh*8;
                int b = (r0 + rloc) & 255;
                b8[mi*2+hh] = b;
                xi8[mi*2+hh] = __ldg(x + b*TT + t + 1);
            }

        float acc[4][2][4];
#pragma unroll
        for (int mi=0;mi<4;mi++)
#pragma unroll
            for(int ni=0;ni<2;ni++)
#pragma unroll
                for(int e=0;e<4;e++) acc[mi][ni][e]=0.f;

        // B prologue: stage (nt=0, kst=0)
        uint4 bv0, bv1;
        {
            int nr0 = cof + brow0, nr1 = nr0 + 64;
            bv0 = (nr0 < VV) ? *(const uint4*)(s_Woutb + (size_t)nr0*640 + bseg) : z4;
            bv1 = (nr1 < VV) ? *(const uint4*)(s_Woutb + (size_t)nr1*640 + bseg) : z4;
        }
        *(uint4*)&Bs[0][brow0][bseg]      = bv0;
        *(uint4*)&Bs[0][brow0 + 64][bseg] = bv1;

        const int NST = LG_NTI * LG_KST;
        for (int gs = 0; gs < NST; gs++){
            __syncthreads();
            const int buf = gs & 1;
            const bool more = (gs + 1) < NST;
            if (more){
                int g2 = gs + 1;
                int nt2 = g2 / LG_KST, kst2 = g2 % LG_KST;
                int nr0 = cof + nt2*128 + brow0, nr1 = nr0 + 64;
                int kc = kst2 * 32;
                bv0 = (nr0 < VV) ? *(const uint4*)(s_Woutb + (size_t)nr0*640 + kc + bseg) : z4;
                bv1 = (nr1 < VV) ? *(const uint4*)(s_Woutb + (size_t)nr1*640 + kc + bseg) : z4;
            }
            const int kst = gs % LG_KST;
            const int kbase = kst * 32;
#pragma unroll
            for (int ks = 0; ks < 32; ks += 16){
                uint32_t af[4][4];
#pragma unroll
                for (int mi = 0; mi < 4; mi++)
                    ldsm4(af[mi][0],af[mi][1],af[mi][2],af[mi][3],
                          smem_addr(&As[mi*16 + (lane & 15)][kbase + ks + ((lane >> 4) << 3)]));
                uint32_t bq[4];
                ldsm4(bq[0],bq[1],bq[2],bq[3],
                      smem_addr(&Bs[buf][warp*16 + ((lane >> 4) << 3) + (lane & 7)]
                                        [ks + (((lane >> 3) & 1) << 3)]));
#pragma unroll
                for (int mi = 0; mi < 4; mi++){
                    mma_bf16(acc[mi][0], af[mi][0],af[mi][1],af[mi][2],af[mi][3], bq[0], bq[1]);
                    mma_bf16(acc[mi][1], af[mi][0],af[mi][1],af[mi][2],af[mi][3], bq[2], bq[3]);
                }
            }
            if (more){
                *(uint4*)&Bs[buf^1][brow0][bseg]      = bv0;
                *(uint4*)&Bs[buf^1][brow0 + 64][bseg] = bv1;
            }
            if (kst == LG_KST - 1){
                int nt = gs / LG_KST;
                int cb = cof + nt*128 + warp*16 + ((lane & 3) << 1);
#pragma unroll
                for (int ni = 0; ni < 2; ni++)
#pragma unroll
                    for (int e2 = 0; e2 < 2; e2++){
                        int c = cb + ni*8 + e2;
                        if (c < VV){
#pragma unroll
                            for (int mi = 0; mi < 4; mi++)
#pragma unroll
                                for (int hh = 0; hh < 2; hh++){
                                    float v = acc[mi][ni][hh*2 + e2]
                                            + __ldg(s_zlog + (size_t)b8[mi*2+hh]*VV + c);
                                    sr[mi*2+hh] += __expf(v - 8.f);
                                    if (c == xi8[mi*2+hh]) tv[mi*2+hh] = v;
                                }
                        }
                    }
#pragma unroll
                for (int mi=0;mi<4;mi++)
#pragma unroll
                    for(int ni=0;ni<2;ni++)
#pragma unroll
                        for(int e=0;e<4;e++) acc[mi][ni][e]=0.f;
            }
        }

#pragma unroll
        for (int i = 0; i < 8; i++){
            sr[i] += __shfl_xor_sync(0xffffffffu, sr[i], 1);
            sr[i] += __shfl_xor_sync(0xffffffffu, sr[i], 2);
            tv[i] += __shfl_xor_sync(0xffffffffu, tv[i], 1);
            tv[i] += __shfl_xor_sync(0xffffffffu, tv[i], 2);
        }
        if ((lane & 3) == 0){
            int qq = lane >> 2;
#pragma unroll
            for (int mi = 0; mi < 4; mi++)
#pragma unroll
                for (int hh = 0; hh < 2; hh++){
                    int rloc = mi*16 + qq + hh*8;
                    s_red[rloc*8 + warp] = sr[mi*2+hh];
                    t_red[rloc*8 + warp] = tv[mi*2+hh];
                }
        }
        __syncthreads();
        if (tid < 64){
            float S = 0.f, T = 0.f;
#pragma unroll
            for (int w = 0; w < 8; w++){ S += s_red[tid*8 + w]; T += t_red[tid*8 + w]; }
            size_t o = (size_t)oct*39*256 + (size_t)t*256 + ((r0 + tid) & 255);
            lgS[o] = S;
            lgT[o] = T;
        }
        __syncthreads();   // all reads of As/Bs/red done before next item overwrites
    }
}

__global__ void lp_sum_kernel(const float* __restrict__ lgS, const float* __restrict__ lgT,
                              float* __restrict__ out){
    int b = threadIdx.x;
    float a = 0.f;
    for (int t = 0; t < 39; t++){
        int r = t*256 + b;
        float S = 0.f, T = 0.f;
#pragma unroll
        for (int o = 0; o < 8; o++){
            S += lgS[o*39*256 + r];
            T += lgT[o*39*256 + r];
        }
        a += T - (8.f + logf(S));
    }
    out[b] = a;
}

// ---------------- host side ----------------
enum { OP_NONE = 0, OP_RELU = 1, OP_TANH = 2 };

static inline void G(int M, int N, int K,
                     const void* A, int lda, const int* aidx,
                     const void* B, int ldb,
                     const float* bias,
                     const float* D, int ldd, int dmask,
                     float* Cf, void* Cb, int ldc, int op)
{
    dim3 grid((N + 63) / 64, (M + 63) / 64);
    gemm_kernel<<<grid, 128>>>(M, N, K,
        (const bf16*)A, lda, aidx,
        (const bf16*)B, ldb, bias, D, ldd, dmask,
        Cf, (bf16*)Cb, ldc, op);
}

extern "C" void kernel_launch(void* const* d_in, const int* in_sizes, int n_in,
                              void* d_out, int out_size)
{
    const float* z    = (const float*)d_in[0];
    const int*   x    = (const int*)  d_in[1];
    const float* emb  = (const float*)d_in[2];
    const float* Wg0  = (const float*)d_in[3];
    const float* bg0  = (const float*)d_in[4];
    const float* Wg1  = (const float*)d_in[5];
    const float* bg1  = (const float*)d_in[6];
    const float* Wout = (const float*)d_in[7];
    const float* bout = (const float*)d_in[8];
    const float* tw1  = (const float*)d_in[9];
    const float* tb1  = (const float*)d_in[10];
    const float* tw2  = (const float*)d_in[11];
    const float* tb2  = (const float*)d_in[12];
    float* out = (float*)d_out;

    void* q;
#define GET(ptr, sym, type) type* ptr; do { cudaGetSymbolAddress(&q, sym); ptr = (type*)q; } while (0)
    GET(p_Wg0b, s_Wg0b, bf16);
    GET(p_Wg1b, s_Wg1b, bf16);
    GET(p_Woutb, s_Woutb, bf16);
    GET(p_tw1b, s_tw1b, bf16);
    GET(p_tw2b, s_tw2b, bf16);
    GET(p_embb, s_embb, bf16);
    GET(p_zb,  s_zb,  bf16);
    GET(p_h0d, s_h0d, bf16);
    GET(p_h1d, s_h1d, bf16);
    GET(p_r,   s_r,   bf16);
    GET(p_c0,  s_c0,  float);
    GET(p_c1,  s_c1,  float);
    GET(p_gz0, s_gz0, float);
    GET(p_hh,  s_hh,  float);
    GET(p_embW, s_embW, float);
    GET(p_zlog, s_zlog, float);
    GET(p_lgS, s_lgS, float);
    GET(p_lgT, s_lgT, float);
    GET(p_idx, s_idx, int);
#undef GET

    // merged fp32->bf16 conversion (single kernel)
    {
        CvtArgs a;
        const float* srcs[7] = {z, emb, Wg0, Wg1, Wout, tw1, tw2};
        bf16* dsts[7] = {p_zb, p_embb, p_Wg0b, p_Wg1b, p_Woutb, p_tw1b, p_tw2b};
        int n4s[7] = {BB*ZZ/4, VV*DD/4, 4*512*1152/4, 4*512*1024/4, VV*640/4,
                      2*2048*128/4, 2*1024*2048/4};
        int cum = 0;
        for (int j = 0; j < 7; j++){
            a.s[j] = (const float4*)srcs[j];
            a.d[j] = (__nv_bfloat162*)dsts[j];
            a.cum[j] = cum;
            cum += n4s[j];
        }
        a.cum[7] = cum;
        cvt_all_kernel<<<592, 256>>>(a);
    }

    reset_kernel<<<1, 128>>>();
    build_idx_kernel<<<(TT * BB + 255) / 256, 256>>>(x, p_idx);

    // init states: hh = tanh(relu(z @ tw1^T + tb1) @ tw2^T + tb2) -> (h, c)
    for (int l = 0; l < 2; l++) {
        G(256, 2048, 128, p_zb, 128, nullptr,
          p_tw1b + (size_t)l * 2048 * 128, 128, tb1 + l * 2048,
          nullptr, 0, 0, nullptr, p_r, 2048, OP_RELU);
        G(256, 1024, 2048, p_r, 2048, nullptr,
          p_tw2b + (size_t)l * 1024 * 2048, 2048, tb2 + l * 1024,
          nullptr, 0, 0, p_hh, nullptr, 1024, OP_TANH);
        if (l == 0) split_init_kernel<<<512, 256>>>(p_hh, p_h0d, p_c0);
        else        split_init_kernel<<<512, 256>>>(p_hh, p_h1d, p_c1);
    }

    // gz0 = z @ W0z^T + bg0
    G(256, 2048, 128, p_zb, 128, nullptr, p_Wg0b + 1024, 1152, bg0,
      nullptr, 0, 0, p_gz0, nullptr, 2048, OP_NONE);

    // zlog = z @ WoutZ^T + bout  (removes z from logits K)
    G(256, 5000, 128, p_zb, 128, nullptr, p_Woutb + 512, 640, bout,
      nullptr, 0, 0, p_zlog, nullptr, 5000, OP_NONE);

    // embW = emb @ W0e^T for ALL vocab rows (5000 x 2048)
    {
        dim3 grid(2048 / 128, (VV + 127) / 128);
        gemm128_kernel<<<grid, 256>>>(VV, 2048, 512,
            p_embb, 512, p_Wg0b + 512, 1152, p_embW, 2048);
    }

    // recurrence only (cells), per-row-block group barriers, H(t) archived
    cudaFuncSetAttribute(loop_kernel,
                         cudaFuncAttributeMaxDynamicSharedMemorySize, LOOP_SMEM);
    loop_kernel<<<NBLK, 256, LOOP_SMEM>>>(bg1);

    // fused logits + log-softmax: 296-CTA balanced grid, 1248 work-stolen items
    cudaFuncSetAttribute(logits_lse_kernel,
                         cudaFuncAttributeMaxDynamicSharedMemorySize, LG_SMEM);
    logits_lse_kernel<<<296, 256, LG_SMEM>>>(x, p_lgS, p_lgT);

    // deterministic per-b sum over t (merging 8 vocab octants)
    lp_sum_kernel<<<1, 256>>>(p_lgS, p_lgT, out);

    (void)in_sizes; (void)n_in; (void)out_size;
}